// round 5
// baseline (speedup 1.0000x reference)
#include <cuda_runtime.h>
#include <math.h>

#define RPB 8   // rows (warps) per block

// ---------------- precomputed tables ----------------
// Interleaved per (t,c): [0:6)=Q (pre-scaled by log2(e)/sqrt(3)), [6:12)=K, [12:18)=V, [18:24)=X
__device__ __align__(16) float g_TAB[34 * 14 * 24];
// wo(36) fw1fold(12) cs1(2) b1c(2) fw2(12) fb2(6) Wf(84) csf(14) bf(14) = 182
__device__ float g_packed[182];

__device__ __forceinline__ int flatmap(int p) {
    if (p < 10) return p;
    if (p == 10) return 11;
    if (p < 21) return p - 11;
    if (p == 21) return 12;
    if (p < 33) { int z = p - 22; return z < 10 ? z : 10; }
    return 13;
}

__global__ void setup_kernel(const float* __restrict__ tok_emb, const float* __restrict__ pos_params,
                             const float* __restrict__ z10, const float* __restrict__ spec,
                             const float* __restrict__ wq, const float* __restrict__ wk,
                             const float* __restrict__ wv,
                             const float* __restrict__ ln1_g, const float* __restrict__ ln1_b,
                             const float* __restrict__ wo, const float* __restrict__ ln2_g,
                             const float* __restrict__ ln2_b,
                             const float* __restrict__ lnf_g, const float* __restrict__ lnf_b,
                             const float* __restrict__ fw1, const float* __restrict__ fb1,
                             const float* __restrict__ fw2, const float* __restrict__ fb2,
                             const float* __restrict__ head_w)
{
    int tid = threadIdx.x;

    if (tid < 182) {
        float v = 0.f;
        if (tid < 36)       v = wo[tid];
        else if (tid < 48) { int u = tid - 36; int j = u >> 1, m = u & 1; v = ln2_g[j] * fw1[j * 2 + m]; }
        else if (tid < 50) { int m = tid - 48; float s = 0.f;
                             for (int j = 0; j < 6; j++) s += ln2_g[j] * fw1[j * 2 + m]; v = s; }
        else if (tid < 52) { int m = tid - 50; float s = fb1[m];
                             for (int j = 0; j < 6; j++) s += ln2_b[j] * fw1[j * 2 + m]; v = s; }
        else if (tid < 64)  v = fw2[tid - 52];
        else if (tid < 70)  v = fb2[tid - 64];
        else if (tid < 154) {
            int u = tid - 70; int n = u / 6, j = u % 6;
            float W = head_w[j * 3 + 0] * tok_emb[n * 3 + 0]
                    + head_w[j * 3 + 1] * tok_emb[n * 3 + 1]
                    + head_w[j * 3 + 2] * tok_emb[n * 3 + 2];
            v = lnf_g[j] * W;
        }
        else if (tid < 168) {
            int n = tid - 154; float s = 0.f;
            for (int j = 0; j < 6; j++) {
                float W = head_w[j * 3 + 0] * tok_emb[n * 3 + 0]
                        + head_w[j * 3 + 1] * tok_emb[n * 3 + 1]
                        + head_w[j * 3 + 2] * tok_emb[n * 3 + 2];
                s += lnf_g[j] * W;
            }
            v = s;
        }
        else {
            int n = tid - 168; float s = 0.f;
            for (int j = 0; j < 6; j++) {
                float W = head_w[j * 3 + 0] * tok_emb[n * 3 + 0]
                        + head_w[j * 3 + 1] * tok_emb[n * 3 + 1]
                        + head_w[j * 3 + 2] * tok_emb[n * 3 + 2];
                s += lnf_b[j] * W;
            }
            v = s;
        }
        g_packed[tid] = v;
    }

    for (int i = tid; i < 34 * 14; i += blockDim.x) {
        int t = i / 14, c = i % 14;
        int f = flatmap(t);
        float p0, p1, p2;
        if (f < 10) {
            float amp = pos_params[0], ph = pos_params[1], sl = pos_params[2], of = pos_params[3];
            float ang = 0.62831853071795864f * (float)f + ph;
            p0 = amp * cosf(ang);
            p1 = amp * sinf(ang);
            p2 = sl * (float)f + of;
        } else if (f == 10) {
            p0 = z10[0]; p1 = z10[1]; p2 = z10[2];
        } else {
            int s = f - 11;
            p0 = spec[s * 3 + 0]; p1 = spec[s * 3 + 1]; p2 = spec[s * 3 + 2];
        }
        float x[6] = { tok_emb[c * 3 + 0], tok_emb[c * 3 + 1], tok_emb[c * 3 + 2], p0, p1, p2 };
        float mu = 0.f;
        #pragma unroll
        for (int j = 0; j < 6; j++) mu += x[j];
        mu *= (1.f / 6.f);
        float var = 0.f;
        #pragma unroll
        for (int j = 0; j < 6; j++) { float d = x[j] - mu; var += d * d; }
        var *= (1.f / 6.f);
        float rs = rsqrtf(var + 1e-5f);
        float h[6];
        #pragma unroll
        for (int j = 0; j < 6; j++) h[j] = (x[j] - mu) * rs * ln1_g[j] + ln1_b[j];

        const float QS = 1.4426950408889634f / 1.7320508075688772f;  // log2(e)/sqrt(3)
        float* T = &g_TAB[i * 24];
        #pragma unroll
        for (int j = 0; j < 6; j++) {
            float q  = h[3] * wq[j] + h[4] * wq[6 + j] + h[5] * wq[12 + j];
            float k  = h[3] * wk[j] + h[4] * wk[6 + j] + h[5] * wk[12 + j];
            float vv = h[0] * wv[j] + h[1] * wv[6 + j] + h[2] * wv[12 + j];
            T[j]      = q * QS;
            T[6 + j]  = k;
            T[12 + j] = vv;
            T[18 + j] = x[j];
        }
    }
}

// ---------------- main kernel ----------------

struct __align__(16) WarpShm {
    float K[6][40];   // SoA keys, stride 40; cols 34..39 zeroed
    float V[6][40];   // SoA values
    float Q[34][8];   // [t][4h+0..2] = q for head h (16B aligned per head)
    float X[34][8];   // [t][0..5]
    float O[34][8];   // [t][4h+0..2] = attention out head h
    // K+V region (480 floats) reused as the 476-float logits buffer in the epilogue
};

__device__ __forceinline__ float ex2f(float x) {
    float y;
    asm("ex2.approx.ftz.f32 %0, %1;" : "=f"(y) : "f"(x));
    return y;
}
__device__ __forceinline__ float rcpf(float x) {
    float y;
    asm("rcp.approx.ftz.f32 %0, %1;" : "=f"(y) : "f"(x));
    return y;
}

// Up to three nested causal-attention tasks per lane sharing one K/V load stream.
// Requires t1 <= t3 <= t2 among active tasks (inactive: pass -1000).
__device__ __forceinline__ void attn_tri(WarpShm& S, int h, int t1, int t2, int t3) {
    int base = 3 * h, qb = 4 * h;
    float4 q2 = *(const float4*)&S.Q[t2][qb];
    float4 q1 = *(const float4*)&S.Q[t1 < 0 ? 0 : t1][qb];
    float4 q3 = *(const float4*)&S.Q[t3 < 0 ? 0 : t3][qb];

    float l1 = 0.f, a10 = 0.f, a11 = 0.f, a12 = 0.f;
    float l2 = 0.f, a20 = 0.f, a21 = 0.f, a22 = 0.f;
    float l3 = 0.f, a30 = 0.f, a31 = 0.f, a32 = 0.f;

    int nb = (t2 >> 2) + 1;
    #pragma unroll 1
    for (int b = 0; b < nb; b++) {
        int k0 = b << 2;
        float4 kx = *(const float4*)&S.K[base + 0][k0];
        float4 ky = *(const float4*)&S.K[base + 1][k0];
        float4 kz = *(const float4*)&S.K[base + 2][k0];
        float4 vx = *(const float4*)&S.V[base + 0][k0];
        float4 vy = *(const float4*)&S.V[base + 1][k0];
        float4 vz = *(const float4*)&S.V[base + 2][k0];

        // task 2 (always active)
        {
            float p0 = ex2f(q2.x * kx.x + q2.y * ky.x + q2.z * kz.x);
            float p1 = ex2f(q2.x * kx.y + q2.y * ky.y + q2.z * kz.y);
            float p2 = ex2f(q2.x * kx.z + q2.y * ky.z + q2.z * kz.z);
            float p3 = ex2f(q2.x * kx.w + q2.y * ky.w + q2.z * kz.w);
            int rem = t2 - k0;
            if (rem < 1) p1 = 0.f;
            if (rem < 2) p2 = 0.f;
            if (rem < 3) p3 = 0.f;
            l2  += (p0 + p1) + (p2 + p3);
            a20 += (p0 * vx.x + p1 * vx.y) + (p2 * vx.z + p3 * vx.w);
            a21 += (p0 * vy.x + p1 * vy.y) + (p2 * vy.z + p3 * vy.w);
            a22 += (p0 * vz.x + p1 * vz.y) + (p2 * vz.z + p3 * vz.w);
        }
        // task 1
        if (k0 <= t1) {
            float p0 = ex2f(q1.x * kx.x + q1.y * ky.x + q1.z * kz.x);
            float p1 = ex2f(q1.x * kx.y + q1.y * ky.y + q1.z * kz.y);
            float p2 = ex2f(q1.x * kx.z + q1.y * ky.z + q1.z * kz.z);
            float p3 = ex2f(q1.x * kx.w + q1.y * ky.w + q1.z * kz.w);
            int rem = t1 - k0;
            if (rem < 1) p1 = 0.f;
            if (rem < 2) p2 = 0.f;
            if (rem < 3) p3 = 0.f;
            l1  += (p0 + p1) + (p2 + p3);
            a10 += (p0 * vx.x + p1 * vx.y) + (p2 * vx.z + p3 * vx.w);
            a11 += (p0 * vy.x + p1 * vy.y) + (p2 * vy.z + p3 * vy.w);
            a12 += (p0 * vz.x + p1 * vz.y) + (p2 * vz.z + p3 * vz.w);
        }
        // task 3
        if (k0 <= t3) {
            float p0 = ex2f(q3.x * kx.x + q3.y * ky.x + q3.z * kz.x);
            float p1 = ex2f(q3.x * kx.y + q3.y * ky.y + q3.z * kz.y);
            float p2 = ex2f(q3.x * kx.z + q3.y * ky.z + q3.z * kz.z);
            float p3 = ex2f(q3.x * kx.w + q3.y * ky.w + q3.z * kz.w);
            int rem = t3 - k0;
            if (rem < 1) p1 = 0.f;
            if (rem < 2) p2 = 0.f;
            if (rem < 3) p3 = 0.f;
            l3  += (p0 + p1) + (p2 + p3);
            a30 += (p0 * vx.x + p1 * vx.y) + (p2 * vx.z + p3 * vx.w);
            a31 += (p0 * vy.x + p1 * vy.y) + (p2 * vy.z + p3 * vy.w);
            a32 += (p0 * vz.x + p1 * vz.y) + (p2 * vz.z + p3 * vz.w);
        }
    }

    {
        float inv = rcpf(l2);
        *(float4*)&S.O[t2][qb] = make_float4(a20 * inv, a21 * inv, a22 * inv, 0.f);
    }
    if (t1 >= 0) {
        float inv = rcpf(l1);
        *(float4*)&S.O[t1][qb] = make_float4(a10 * inv, a11 * inv, a12 * inv, 0.f);
    }
    if (t3 >= 0) {
        float inv = rcpf(l3);
        *(float4*)&S.O[t3][qb] = make_float4(a30 * inv, a31 * inv, a32 * inv, 0.f);
    }
}

// Per-position epilogue with LN gains/biases folded into FFN/logit weights.
__device__ __forceinline__ void epilogue_pos(WarpShm& R, const float* cw, int t) {
    float4 xa = *(const float4*)&R.X[t][0];
    float2 xb = *(const float2*)&R.X[t][4];
    float4 oa = *(const float4*)&R.O[t][0];
    float4 ob = *(const float4*)&R.O[t][4];
    float o0 = oa.x, o1 = oa.y, o2 = oa.z, o3 = ob.x, o4 = ob.y, o5 = ob.z;
    float xv[6] = { xa.x, xa.y, xa.z, xa.w, xb.x, xb.y };
    float y[6];
    #pragma unroll
    for (int j = 0; j < 6; j++)
        y[j] = xv[j] + o0 * cw[j] + o1 * cw[6 + j] + o2 * cw[12 + j]
             + o3 * cw[18 + j] + o4 * cw[24 + j] + o5 * cw[30 + j];

    // LN2 stats (gain/bias folded into FFN weights)
    float mu = (y[0] + y[1] + y[2] + y[3] + y[4] + y[5]) * (1.f / 6.f);
    float var = 0.f;
    #pragma unroll
    for (int j = 0; j < 6; j++) { float d = y[j] - mu; var += d * d; }
    float rs = rsqrtf(var * (1.f / 6.f) + 1e-5f);

    float dot0 = 0.f, dot1 = 0.f;
    #pragma unroll
    for (int j = 0; j < 6; j++) { dot0 += y[j] * cw[36 + 2 * j]; dot1 += y[j] * cw[37 + 2 * j]; }
    float f0 = rs * (dot0 - mu * cw[48]) + cw[50];
    float f1 = rs * (dot1 - mu * cw[49]) + cw[51];
    float g0 = 0.5f * f0 * (1.f + erff(f0 * 0.70710678118654752f));
    float g1 = 0.5f * f1 * (1.f + erff(f1 * 0.70710678118654752f));
    float z[6];
    #pragma unroll
    for (int j = 0; j < 6; j++) z[j] = y[j] + g0 * cw[52 + j] + g1 * cw[58 + j] + cw[64 + j];

    // LNf stats (gain/bias folded into logit weights)
    float mu2 = (z[0] + z[1] + z[2] + z[3] + z[4] + z[5]) * (1.f / 6.f);
    float var2 = 0.f;
    #pragma unroll
    for (int j = 0; j < 6; j++) { float d = z[j] - mu2; var2 += d * d; }
    float rs2 = rsqrtf(var2 * (1.f / 6.f) + 1e-5f);

    float* Lp = (float*)&R.K[0][0];
    #pragma unroll
    for (int n = 0; n < 14; n++) {
        const float* Wn = &cw[70 + n * 6];
        float d = z[0] * Wn[0] + z[1] * Wn[1] + z[2] * Wn[2]
                + z[3] * Wn[3] + z[4] * Wn[4] + z[5] * Wn[5];
        Lp[t * 14 + n] = rs2 * (d - mu2 * cw[154 + n]) + cw[168 + n];
    }
}

__global__ void __launch_bounds__(256, 3)
fwd_kernel(const int* __restrict__ idx, float* __restrict__ out, int nrows)
{
    __shared__ WarpShm shm[RPB];
    __shared__ float cw[182];

    int tid = threadIdx.x;
    for (int i = tid; i < 182; i += 256) cw[i] = g_packed[i];
    __syncthreads();   // the only block-wide barrier: cw ready

    int w = tid >> 5, lane = tid & 31;
    int row = blockIdx.x * RPB + w;
    if (row >= nrows) return;
    WarpShm& S = shm[w];

    // ---- phase 2: gather per-row q/k/v/x from the interleaved table ----
    for (int i = lane; i < 36; i += 32) {   // zero K/V pad columns 34..39
        int j = i / 6, tt = 34 + i % 6;
        S.K[j][tt] = 0.f;
        S.V[j][tt] = 0.f;
    }
    for (int t = lane; t < 34; t += 32) {
        int c = idx[(size_t)row * 34 + t];
        const float4* Tp = (const float4*)&g_TAB[(t * 14 + c) * 24];
        float4 v0 = Tp[0], v1 = Tp[1], v2 = Tp[2], v3 = Tp[3], v4 = Tp[4], v5 = Tp[5];
        // Q: head0 = v0.xyz, head1 = v0.w, v1.xy
        *(float4*)&S.Q[t][0] = make_float4(v0.x, v0.y, v0.z, 0.f);
        *(float4*)&S.Q[t][4] = make_float4(v0.w, v1.x, v1.y, 0.f);
        // K = v1.zw, v2.xyzw (transposed scatter)
        S.K[0][t] = v1.z; S.K[1][t] = v1.w; S.K[2][t] = v2.x;
        S.K[3][t] = v2.y; S.K[4][t] = v2.z; S.K[5][t] = v2.w;
        // V = v3.xyzw, v4.xy
        S.V[0][t] = v3.x; S.V[1][t] = v3.y; S.V[2][t] = v3.z;
        S.V[3][t] = v3.w; S.V[4][t] = v4.x; S.V[5][t] = v4.y;
        // X = v4.zw, v5.xyzw
        *(float4*)&S.X[t][0] = make_float4(v4.z, v4.w, v5.x, v5.y);
        *(float2*)&S.X[t][4] = make_float2(v5.z, v5.w);
    }
    __syncwarp();

    // ---- phase 3: causal 2-head attention, tri-task lanes ----
    {
        int hh = lane >> 4;
        int tt = lane & 15;
        int t1 = tt;                                   // 0..15
        int t2 = 33 - tt;                              // 18..33
        int t3 = (tt >= 14) ? (31 - tt) : -1000;       // lanes 14,15 -> 17,16
        attn_tri(S, hh, t1, t2, t3);
    }
    __syncwarp();

    // ---- phase 4: per-warp epilogue over this row's 34 positions ----
    for (int t = lane; t < 34; t += 32)
        epilogue_pos(S, cw, t);
    __syncwarp();

    // ---- phase 5: per-warp coalesced float4 store (119 float4 per row) ----
    float4* outv = (float4*)out + (size_t)row * 119;
    const float4* Lv = (const float4*)&S.K[0][0];
    for (int q = lane; q < 119; q += 32)
        outv[q] = Lv[q];
}

// ---------------- launch ----------------

extern "C" void kernel_launch(void* const* d_in, const int* in_sizes, int n_in,
                              void* d_out, int out_size)
{
    const int* idx         = (const int*)d_in[0];
    const float* tok_emb   = (const float*)d_in[1];
    const float* pos_params= (const float*)d_in[2];
    const float* z10_enc   = (const float*)d_in[3];
    const float* special   = (const float*)d_in[4];
    const float* wq        = (const float*)d_in[5];
    const float* wk        = (const float*)d_in[6];
    const float* wv        = (const float*)d_in[7];
    const float* wo        = (const float*)d_in[8];
    const float* ln1_g     = (const float*)d_in[9];
    const float* ln1_b     = (const float*)d_in[10];
    const float* ln2_g     = (const float*)d_in[11];
    const float* ln2_b     = (const float*)d_in[12];
    const float* lnf_g     = (const float*)d_in[13];
    const float* lnf_b     = (const float*)d_in[14];
    const float* ffn_w1    = (const float*)d_in[15];
    const float* ffn_b1    = (const float*)d_in[16];
    const float* ffn_w2    = (const float*)d_in[17];
    const float* ffn_b2    = (const float*)d_in[18];
    const float* head_w    = (const float*)d_in[19];

    int nrows = in_sizes[0] / 34;

    setup_kernel<<<1, 512>>>(tok_emb, pos_params, z10_enc, special,
                             wq, wk, wv, ln1_g, ln1_b,
                             wo, ln2_g, ln2_b, lnf_g, lnf_b,
                             ffn_w1, ffn_b1, ffn_w2, ffn_b2, head_w);

    int grid = (nrows + RPB - 1) / RPB;
    fwd_kernel<<<grid, 256>>>(idx, (float*)d_out, nrows);
}

// round 6
// speedup vs baseline: 1.1014x; 1.1014x over previous
#include <cuda_runtime.h>
#include <math.h>

#define RPB 8   // rows (warps) per block

// ---------------- precomputed tables ----------------
// Interleaved per (t,c): [0:6)=Q (pre-scaled by log2(e)/sqrt(3)), [6:12)=K, [12:18)=V, [18:24)=X
__device__ __align__(16) float g_TAB[34 * 14 * 24];
// wo(36) fw1fold(12) cs1(2) b1c(2) fw2(12) fb2(6) Wf(84) csf(14) bf(14) = 182
__device__ float g_packed[182];

__device__ __forceinline__ int flatmap(int p) {
    if (p < 10) return p;
    if (p == 10) return 11;
    if (p < 21) return p - 11;
    if (p == 21) return 12;
    if (p < 33) { int z = p - 22; return z < 10 ? z : 10; }
    return 13;
}

__global__ void setup_kernel(const float* __restrict__ tok_emb, const float* __restrict__ pos_params,
                             const float* __restrict__ z10, const float* __restrict__ spec,
                             const float* __restrict__ wq, const float* __restrict__ wk,
                             const float* __restrict__ wv,
                             const float* __restrict__ ln1_g, const float* __restrict__ ln1_b,
                             const float* __restrict__ wo, const float* __restrict__ ln2_g,
                             const float* __restrict__ ln2_b,
                             const float* __restrict__ lnf_g, const float* __restrict__ lnf_b,
                             const float* __restrict__ fw1, const float* __restrict__ fb1,
                             const float* __restrict__ fw2, const float* __restrict__ fb2,
                             const float* __restrict__ head_w)
{
    int tid = threadIdx.x;

    if (tid < 182) {
        float v = 0.f;
        if (tid < 36)       v = wo[tid];
        else if (tid < 48) { int u = tid - 36; int j = u >> 1, m = u & 1; v = ln2_g[j] * fw1[j * 2 + m]; }
        else if (tid < 50) { int m = tid - 48; float s = 0.f;
                             for (int j = 0; j < 6; j++) s += ln2_g[j] * fw1[j * 2 + m]; v = s; }
        else if (tid < 52) { int m = tid - 50; float s = fb1[m];
                             for (int j = 0; j < 6; j++) s += ln2_b[j] * fw1[j * 2 + m]; v = s; }
        else if (tid < 64)  v = fw2[tid - 52];
        else if (tid < 70)  v = fb2[tid - 64];
        else if (tid < 154) {
            int u = tid - 70; int n = u / 6, j = u % 6;
            float W = head_w[j * 3 + 0] * tok_emb[n * 3 + 0]
                    + head_w[j * 3 + 1] * tok_emb[n * 3 + 1]
                    + head_w[j * 3 + 2] * tok_emb[n * 3 + 2];
            v = lnf_g[j] * W;
        }
        else if (tid < 168) {
            int n = tid - 154; float s = 0.f;
            for (int j = 0; j < 6; j++) {
                float W = head_w[j * 3 + 0] * tok_emb[n * 3 + 0]
                        + head_w[j * 3 + 1] * tok_emb[n * 3 + 1]
                        + head_w[j * 3 + 2] * tok_emb[n * 3 + 2];
                s += lnf_g[j] * W;
            }
            v = s;
        }
        else {
            int n = tid - 168; float s = 0.f;
            for (int j = 0; j < 6; j++) {
                float W = head_w[j * 3 + 0] * tok_emb[n * 3 + 0]
                        + head_w[j * 3 + 1] * tok_emb[n * 3 + 1]
                        + head_w[j * 3 + 2] * tok_emb[n * 3 + 2];
                s += lnf_b[j] * W;
            }
            v = s;
        }
        g_packed[tid] = v;
    }

    for (int i = tid; i < 34 * 14; i += blockDim.x) {
        int t = i / 14, c = i % 14;
        int f = flatmap(t);
        float p0, p1, p2;
        if (f < 10) {
            float amp = pos_params[0], ph = pos_params[1], sl = pos_params[2], of = pos_params[3];
            float ang = 0.62831853071795864f * (float)f + ph;
            p0 = amp * cosf(ang);
            p1 = amp * sinf(ang);
            p2 = sl * (float)f + of;
        } else if (f == 10) {
            p0 = z10[0]; p1 = z10[1]; p2 = z10[2];
        } else {
            int s = f - 11;
            p0 = spec[s * 3 + 0]; p1 = spec[s * 3 + 1]; p2 = spec[s * 3 + 2];
        }
        float x[6] = { tok_emb[c * 3 + 0], tok_emb[c * 3 + 1], tok_emb[c * 3 + 2], p0, p1, p2 };
        float mu = 0.f;
        #pragma unroll
        for (int j = 0; j < 6; j++) mu += x[j];
        mu *= (1.f / 6.f);
        float var = 0.f;
        #pragma unroll
        for (int j = 0; j < 6; j++) { float d = x[j] - mu; var += d * d; }
        var *= (1.f / 6.f);
        float rs = rsqrtf(var + 1e-5f);
        float h[6];
        #pragma unroll
        for (int j = 0; j < 6; j++) h[j] = (x[j] - mu) * rs * ln1_g[j] + ln1_b[j];

        const float QS = 1.4426950408889634f / 1.7320508075688772f;  // log2(e)/sqrt(3)
        float* T = &g_TAB[i * 24];
        #pragma unroll
        for (int j = 0; j < 6; j++) {
            float q  = h[3] * wq[j] + h[4] * wq[6 + j] + h[5] * wq[12 + j];
            float k  = h[3] * wk[j] + h[4] * wk[6 + j] + h[5] * wk[12 + j];
            float vv = h[0] * wv[j] + h[1] * wv[6 + j] + h[2] * wv[12 + j];
            T[j]      = q * QS;
            T[6 + j]  = k;
            T[12 + j] = vv;
            T[18 + j] = x[j];
        }
    }
}

// ---------------- main kernel ----------------

struct __align__(16) WarpShm {
    float K[6][40];   // SoA keys, stride 40; cols 34..39 zeroed
    float V[6][40];   // SoA values
    float Q[34][8];   // [t][4h+0..2] = q for head h (16B aligned per head)
    float X[34][8];   // [t][0..5]
    float O[34][8];   // [t][4h+0..2] = attention out head h
    // K+V region (480 floats) reused as the 476-float logits buffer in the epilogue
};

__device__ __forceinline__ float ex2f(float x) {
    float y;
    asm("ex2.approx.ftz.f32 %0, %1;" : "=f"(y) : "f"(x));
    return y;
}
__device__ __forceinline__ float rcpf(float x) {
    float y;
    asm("rcp.approx.ftz.f32 %0, %1;" : "=f"(y) : "f"(x));
    return y;
}

// One 4-key score/accumulate group. rem = t - k0 (>= 0 when called).
__device__ __forceinline__ void group4(
    const float4& kx, const float4& ky, const float4& kz,
    const float4& vx, const float4& vy, const float4& vz,
    const float4& q, int rem,
    float& l, float& a0, float& a1, float& a2)
{
    float p0 = ex2f(q.x * kx.x + q.y * ky.x + q.z * kz.x);
    float p1 = ex2f(q.x * kx.y + q.y * ky.y + q.z * kz.y);
    float p2 = ex2f(q.x * kx.z + q.y * ky.z + q.z * kz.z);
    float p3 = ex2f(q.x * kx.w + q.y * ky.w + q.z * kz.w);
    if (rem < 1) p1 = 0.f;
    if (rem < 2) p2 = 0.f;
    if (rem < 3) p3 = 0.f;
    l  += (p0 + p1) + (p2 + p3);
    a0 += (p0 * vx.x + p1 * vx.y) + (p2 * vx.z + p3 * vx.w);
    a1 += (p0 * vy.x + p1 * vy.y) + (p2 * vy.z + p3 * vy.w);
    a2 += (p0 * vz.x + p1 * vz.y) + (p2 * vz.z + p3 * vz.w);
}

// Up to three nested causal-attention tasks per lane sharing one K/V load stream,
// processed 8 keys per outer iteration (two independent 4-key groups).
// Requires t1 <= t3 <= t2 among active tasks (inactive: pass -1000).
__device__ __forceinline__ void attn_tri(WarpShm& S, int h, int t1, int t2, int t3) {
    int base = 3 * h, qb = 4 * h;
    float4 q2 = *(const float4*)&S.Q[t2][qb];
    float4 q1 = *(const float4*)&S.Q[t1 < 0 ? 0 : t1][qb];
    float4 q3 = *(const float4*)&S.Q[t3 < 0 ? 0 : t3][qb];

    float l1 = 0.f, a10 = 0.f, a11 = 0.f, a12 = 0.f;
    float l2 = 0.f, a20 = 0.f, a21 = 0.f, a22 = 0.f;
    float l3 = 0.f, a30 = 0.f, a31 = 0.f, a32 = 0.f;

    int nbo = (t2 >> 3) + 1;
    #pragma unroll 1
    for (int b = 0; b < nbo; b++) {
        int k0 = b << 3;
        // 8-key tile: group A = keys k0..k0+3, group B = keys k0+4..k0+7
        // (pad columns 34..39 are zeroed, so B loads are always in-bounds)
        float4 kxA = *(const float4*)&S.K[base + 0][k0];
        float4 kyA = *(const float4*)&S.K[base + 1][k0];
        float4 kzA = *(const float4*)&S.K[base + 2][k0];
        float4 vxA = *(const float4*)&S.V[base + 0][k0];
        float4 vyA = *(const float4*)&S.V[base + 1][k0];
        float4 vzA = *(const float4*)&S.V[base + 2][k0];
        float4 kxB = *(const float4*)&S.K[base + 0][k0 + 4];
        float4 kyB = *(const float4*)&S.K[base + 1][k0 + 4];
        float4 kzB = *(const float4*)&S.K[base + 2][k0 + 4];
        float4 vxB = *(const float4*)&S.V[base + 0][k0 + 4];
        float4 vyB = *(const float4*)&S.V[base + 1][k0 + 4];
        float4 vzB = *(const float4*)&S.V[base + 2][k0 + 4];

        // task 2 (k0 <= t2 guaranteed by nbo)
        group4(kxA, kyA, kzA, vxA, vyA, vzA, q2, t2 - k0, l2, a20, a21, a22);
        if (k0 + 4 <= t2)
            group4(kxB, kyB, kzB, vxB, vyB, vzB, q2, t2 - k0 - 4, l2, a20, a21, a22);
        // task 1
        if (k0 <= t1)
            group4(kxA, kyA, kzA, vxA, vyA, vzA, q1, t1 - k0, l1, a10, a11, a12);
        if (k0 + 4 <= t1)
            group4(kxB, kyB, kzB, vxB, vyB, vzB, q1, t1 - k0 - 4, l1, a10, a11, a12);
        // task 3
        if (k0 <= t3)
            group4(kxA, kyA, kzA, vxA, vyA, vzA, q3, t3 - k0, l3, a30, a31, a32);
        if (k0 + 4 <= t3)
            group4(kxB, kyB, kzB, vxB, vyB, vzB, q3, t3 - k0 - 4, l3, a30, a31, a32);
    }

    {
        float inv = rcpf(l2);
        *(float4*)&S.O[t2][qb] = make_float4(a20 * inv, a21 * inv, a22 * inv, 0.f);
    }
    if (t1 >= 0) {
        float inv = rcpf(l1);
        *(float4*)&S.O[t1][qb] = make_float4(a10 * inv, a11 * inv, a12 * inv, 0.f);
    }
    if (t3 >= 0) {
        float inv = rcpf(l3);
        *(float4*)&S.O[t3][qb] = make_float4(a30 * inv, a31 * inv, a32 * inv, 0.f);
    }
}

// Per-position epilogue with LN gains/biases folded into FFN/logit weights.
__device__ __forceinline__ void epilogue_pos(WarpShm& R, const float* cw, int t) {
    float4 xa = *(const float4*)&R.X[t][0];
    float2 xb = *(const float2*)&R.X[t][4];
    float4 oa = *(const float4*)&R.O[t][0];
    float4 ob = *(const float4*)&R.O[t][4];
    float o0 = oa.x, o1 = oa.y, o2 = oa.z, o3 = ob.x, o4 = ob.y, o5 = ob.z;
    float xv[6] = { xa.x, xa.y, xa.z, xa.w, xb.x, xb.y };
    float y[6];
    #pragma unroll
    for (int j = 0; j < 6; j++)
        y[j] = xv[j] + o0 * cw[j] + o1 * cw[6 + j] + o2 * cw[12 + j]
             + o3 * cw[18 + j] + o4 * cw[24 + j] + o5 * cw[30 + j];

    // LN2 stats (gain/bias folded into FFN weights)
    float mu = (y[0] + y[1] + y[2] + y[3] + y[4] + y[5]) * (1.f / 6.f);
    float var = 0.f;
    #pragma unroll
    for (int j = 0; j < 6; j++) { float d = y[j] - mu; var += d * d; }
    float rs = rsqrtf(var * (1.f / 6.f) + 1e-5f);

    float dot0 = 0.f, dot1 = 0.f;
    #pragma unroll
    for (int j = 0; j < 6; j++) { dot0 += y[j] * cw[36 + 2 * j]; dot1 += y[j] * cw[37 + 2 * j]; }
    float f0 = rs * (dot0 - mu * cw[48]) + cw[50];
    float f1 = rs * (dot1 - mu * cw[49]) + cw[51];
    float g0 = 0.5f * f0 * (1.f + erff(f0 * 0.70710678118654752f));
    float g1 = 0.5f * f1 * (1.f + erff(f1 * 0.70710678118654752f));
    float z[6];
    #pragma unroll
    for (int j = 0; j < 6; j++) z[j] = y[j] + g0 * cw[52 + j] + g1 * cw[58 + j] + cw[64 + j];

    // LNf stats (gain/bias folded into logit weights)
    float mu2 = (z[0] + z[1] + z[2] + z[3] + z[4] + z[5]) * (1.f / 6.f);
    float var2 = 0.f;
    #pragma unroll
    for (int j = 0; j < 6; j++) { float d = z[j] - mu2; var2 += d * d; }
    float rs2 = rsqrtf(var2 * (1.f / 6.f) + 1e-5f);

    float* Lp = (float*)&R.K[0][0];
    #pragma unroll
    for (int n = 0; n < 14; n++) {
        const float* Wn = &cw[70 + n * 6];
        float d = z[0] * Wn[0] + z[1] * Wn[1] + z[2] * Wn[2]
                + z[3] * Wn[3] + z[4] * Wn[4] + z[5] * Wn[5];
        Lp[t * 14 + n] = rs2 * (d - mu2 * cw[154 + n]) + cw[168 + n];
    }
}

__global__ void __launch_bounds__(256, 2)
fwd_kernel(const int* __restrict__ idx, float* __restrict__ out, int nrows)
{
    __shared__ WarpShm shm[RPB];
    __shared__ float cw[182];

    int tid = threadIdx.x;
    for (int i = tid; i < 182; i += 256) cw[i] = g_packed[i];
    __syncthreads();   // the only block-wide barrier: cw ready

    int w = tid >> 5, lane = tid & 31;
    int row = blockIdx.x * RPB + w;
    if (row >= nrows) return;
    WarpShm& S = shm[w];

    // ---- phase 2: gather per-row q/k/v/x from the interleaved table ----
    for (int i = lane; i < 36; i += 32) {   // zero K/V pad columns 34..39
        int j = i / 6, tt = 34 + i % 6;
        S.K[j][tt] = 0.f;
        S.V[j][tt] = 0.f;
    }
    for (int t = lane; t < 34; t += 32) {
        int c = idx[(size_t)row * 34 + t];
        const float4* Tp = (const float4*)&g_TAB[(t * 14 + c) * 24];
        float4 v0 = Tp[0], v1 = Tp[1], v2 = Tp[2], v3 = Tp[3], v4 = Tp[4], v5 = Tp[5];
        // Q: head0 = v0.xyz, head1 = v0.w, v1.xy
        *(float4*)&S.Q[t][0] = make_float4(v0.x, v0.y, v0.z, 0.f);
        *(float4*)&S.Q[t][4] = make_float4(v0.w, v1.x, v1.y, 0.f);
        // K = v1.zw, v2.xyzw (transposed scatter)
        S.K[0][t] = v1.z; S.K[1][t] = v1.w; S.K[2][t] = v2.x;
        S.K[3][t] = v2.y; S.K[4][t] = v2.z; S.K[5][t] = v2.w;
        // V = v3.xyzw, v4.xy
        S.V[0][t] = v3.x; S.V[1][t] = v3.y; S.V[2][t] = v3.z;
        S.V[3][t] = v3.w; S.V[4][t] = v4.x; S.V[5][t] = v4.y;
        // X = v4.zw, v5.xyzw
        *(float4*)&S.X[t][0] = make_float4(v4.z, v4.w, v5.x, v5.y);
        *(float2*)&S.X[t][4] = make_float2(v5.z, v5.w);
    }
    __syncwarp();

    // ---- phase 3: causal 2-head attention, tri-task lanes, 8 keys/iter ----
    {
        int hh = lane >> 4;
        int tt = lane & 15;
        int t1 = tt;                                   // 0..15
        int t2 = 33 - tt;                              // 18..33
        int t3 = (tt >= 14) ? (31 - tt) : -1000;       // lanes 14,15 -> 17,16
        attn_tri(S, hh, t1, t2, t3);
    }
    __syncwarp();

    // ---- phase 4: per-warp epilogue over this row's 34 positions ----
    for (int t = lane; t < 34; t += 32)
        epilogue_pos(S, cw, t);
    __syncwarp();

    // ---- phase 5: per-warp coalesced float4 store (119 float4 per row) ----
    float4* outv = (float4*)out + (size_t)row * 119;
    const float4* Lv = (const float4*)&S.K[0][0];
    for (int q = lane; q < 119; q += 32)
        outv[q] = Lv[q];
}

// ---------------- launch ----------------

extern "C" void kernel_launch(void* const* d_in, const int* in_sizes, int n_in,
                              void* d_out, int out_size)
{
    const int* idx         = (const int*)d_in[0];
    const float* tok_emb   = (const float*)d_in[1];
    const float* pos_params= (const float*)d_in[2];
    const float* z10_enc   = (const float*)d_in[3];
    const float* special   = (const float*)d_in[4];
    const float* wq        = (const float*)d_in[5];
    const float* wk        = (const float*)d_in[6];
    const float* wv        = (const float*)d_in[7];
    const float* wo        = (const float*)d_in[8];
    const float* ln1_g     = (const float*)d_in[9];
    const float* ln1_b     = (const float*)d_in[10];
    const float* ln2_g     = (const float*)d_in[11];
    const float* ln2_b     = (const float*)d_in[12];
    const float* lnf_g     = (const float*)d_in[13];
    const float* lnf_b     = (const float*)d_in[14];
    const float* ffn_w1    = (const float*)d_in[15];
    const float* ffn_b1    = (const float*)d_in[16];
    const float* ffn_w2    = (const float*)d_in[17];
    const float* ffn_b2    = (const float*)d_in[18];
    const float* head_w    = (const float*)d_in[19];

    int nrows = in_sizes[0] / 34;

    setup_kernel<<<1, 512>>>(tok_emb, pos_params, z10_enc, special,
                             wq, wk, wv, ln1_g, ln1_b,
                             wo, ln2_g, ln2_b, lnf_g, lnf_b,
                             ffn_w1, ffn_b1, ffn_w2, ffn_b2, head_w);

    int grid = (nrows + RPB - 1) / RPB;
    fwd_kernel<<<grid, 256>>>(idx, (float*)d_out, nrows);
}

// round 7
// speedup vs baseline: 1.6286x; 1.4786x over previous
#include <cuda_runtime.h>
#include <math.h>

#define RPB 4   // rows per block (2 warps per row: one per head)

// ---------------- precomputed tables ----------------
// Interleaved per (t,c): [0:6)=Q (pre-scaled by log2(e)/sqrt(3)), [6:12)=K, [12:18)=V, [18:24)=X
__device__ __align__(16) float g_TAB[34 * 14 * 24];
// wo(36) fw1fold(12) cs1(2) b1c(2) fw2(12) fb2(6) Wf(84) csf(14) bf(14) = 182
__device__ float g_packed[182];

__device__ __forceinline__ int flatmap(int p) {
    if (p < 10) return p;
    if (p == 10) return 11;
    if (p < 21) return p - 11;
    if (p == 21) return 12;
    if (p < 33) { int z = p - 22; return z < 10 ? z : 10; }
    return 13;
}

__global__ void setup_kernel(const float* __restrict__ tok_emb, const float* __restrict__ pos_params,
                             const float* __restrict__ z10, const float* __restrict__ spec,
                             const float* __restrict__ wq, const float* __restrict__ wk,
                             const float* __restrict__ wv,
                             const float* __restrict__ ln1_g, const float* __restrict__ ln1_b,
                             const float* __restrict__ wo, const float* __restrict__ ln2_g,
                             const float* __restrict__ ln2_b,
                             const float* __restrict__ lnf_g, const float* __restrict__ lnf_b,
                             const float* __restrict__ fw1, const float* __restrict__ fb1,
                             const float* __restrict__ fw2, const float* __restrict__ fb2,
                             const float* __restrict__ head_w)
{
    int tid = threadIdx.x;

    if (tid < 182) {
        float v = 0.f;
        if (tid < 36)       v = wo[tid];
        else if (tid < 48) { int u = tid - 36; int j = u >> 1, m = u & 1; v = ln2_g[j] * fw1[j * 2 + m]; }
        else if (tid < 50) { int m = tid - 48; float s = 0.f;
                             for (int j = 0; j < 6; j++) s += ln2_g[j] * fw1[j * 2 + m]; v = s; }
        else if (tid < 52) { int m = tid - 50; float s = fb1[m];
                             for (int j = 0; j < 6; j++) s += ln2_b[j] * fw1[j * 2 + m]; v = s; }
        else if (tid < 64)  v = fw2[tid - 52];
        else if (tid < 70)  v = fb2[tid - 64];
        else if (tid < 154) {
            int u = tid - 70; int n = u / 6, j = u % 6;
            float W = head_w[j * 3 + 0] * tok_emb[n * 3 + 0]
                    + head_w[j * 3 + 1] * tok_emb[n * 3 + 1]
                    + head_w[j * 3 + 2] * tok_emb[n * 3 + 2];
            v = lnf_g[j] * W;
        }
        else if (tid < 168) {
            int n = tid - 154; float s = 0.f;
            for (int j = 0; j < 6; j++) {
                float W = head_w[j * 3 + 0] * tok_emb[n * 3 + 0]
                        + head_w[j * 3 + 1] * tok_emb[n * 3 + 1]
                        + head_w[j * 3 + 2] * tok_emb[n * 3 + 2];
                s += lnf_g[j] * W;
            }
            v = s;
        }
        else {
            int n = tid - 168; float s = 0.f;
            for (int j = 0; j < 6; j++) {
                float W = head_w[j * 3 + 0] * tok_emb[n * 3 + 0]
                        + head_w[j * 3 + 1] * tok_emb[n * 3 + 1]
                        + head_w[j * 3 + 2] * tok_emb[n * 3 + 2];
                s += lnf_b[j] * W;
            }
            v = s;
        }
        g_packed[tid] = v;
    }

    for (int i = tid; i < 34 * 14; i += blockDim.x) {
        int t = i / 14, c = i % 14;
        int f = flatmap(t);
        float p0, p1, p2;
        if (f < 10) {
            float amp = pos_params[0], ph = pos_params[1], sl = pos_params[2], of = pos_params[3];
            float ang = 0.62831853071795864f * (float)f + ph;
            p0 = amp * cosf(ang);
            p1 = amp * sinf(ang);
            p2 = sl * (float)f + of;
        } else if (f == 10) {
            p0 = z10[0]; p1 = z10[1]; p2 = z10[2];
        } else {
            int s = f - 11;
            p0 = spec[s * 3 + 0]; p1 = spec[s * 3 + 1]; p2 = spec[s * 3 + 2];
        }
        float x[6] = { tok_emb[c * 3 + 0], tok_emb[c * 3 + 1], tok_emb[c * 3 + 2], p0, p1, p2 };
        float mu = 0.f;
        #pragma unroll
        for (int j = 0; j < 6; j++) mu += x[j];
        mu *= (1.f / 6.f);
        float var = 0.f;
        #pragma unroll
        for (int j = 0; j < 6; j++) { float d = x[j] - mu; var += d * d; }
        var *= (1.f / 6.f);
        float rs = rsqrtf(var + 1e-5f);
        float h[6];
        #pragma unroll
        for (int j = 0; j < 6; j++) h[j] = (x[j] - mu) * rs * ln1_g[j] + ln1_b[j];

        const float QS = 1.4426950408889634f / 1.7320508075688772f;  // log2(e)/sqrt(3)
        float* T = &g_TAB[i * 24];
        #pragma unroll
        for (int j = 0; j < 6; j++) {
            float q  = h[3] * wq[j] + h[4] * wq[6 + j] + h[5] * wq[12 + j];
            float k  = h[3] * wk[j] + h[4] * wk[6 + j] + h[5] * wk[12 + j];
            float vv = h[0] * wv[j] + h[1] * wv[6 + j] + h[2] * wv[12 + j];
            T[j]      = q * QS;
            T[6 + j]  = k;
            T[12 + j] = vv;
            T[18 + j] = x[j];
        }
    }
}

// ---------------- main kernel ----------------

struct __align__(16) RowShm {
    float K[6][40];   // SoA keys, stride 40; cols 34..39 zeroed
    float V[6][40];   // SoA values
    float Q[34][8];   // [t][4h+0..2] = q for head h (16B aligned per head)
    float X[34][8];   // [t][0..5]
    float O[34][8];   // [t][4h+0..2] = attention out head h
    // K+V region (480 floats) reused as the 476-float logits buffer in the epilogue
};

__device__ __forceinline__ float ex2f(float x) {
    float y;
    asm("ex2.approx.ftz.f32 %0, %1;" : "=f"(y) : "f"(x));
    return y;
}
__device__ __forceinline__ float rcpf(float x) {
    float y;
    asm("rcp.approx.ftz.f32 %0, %1;" : "=f"(y) : "f"(x));
    return y;
}

// One 4-key score/accumulate group. rem = t - k0 (>= 0 when called).
__device__ __forceinline__ void group4(
    const float4& kx, const float4& ky, const float4& kz,
    const float4& vx, const float4& vy, const float4& vz,
    const float4& q, int rem,
    float& l, float& a0, float& a1, float& a2)
{
    float p0 = ex2f(q.x * kx.x + q.y * ky.x + q.z * kz.x);
    float p1 = ex2f(q.x * kx.y + q.y * ky.y + q.z * kz.y);
    float p2 = ex2f(q.x * kx.z + q.y * ky.z + q.z * kz.z);
    float p3 = ex2f(q.x * kx.w + q.y * ky.w + q.z * kz.w);
    if (rem < 1) p1 = 0.f;
    if (rem < 2) p2 = 0.f;
    if (rem < 3) p3 = 0.f;
    l  += (p0 + p1) + (p2 + p3);
    a0 += (p0 * vx.x + p1 * vx.y) + (p2 * vx.z + p3 * vx.w);
    a1 += (p0 * vy.x + p1 * vy.y) + (p2 * vy.z + p3 * vy.w);
    a2 += (p0 * vz.x + p1 * vz.y) + (p2 * vz.z + p3 * vz.w);
}

// Single causal-attention task for query t, head h; 8 keys per iteration.
__device__ __forceinline__ void attn_one(RowShm& S, int h, int t) {
    int base = 3 * h, qb = 4 * h;
    float4 q = *(const float4*)&S.Q[t][qb];
    float l = 0.f, a0 = 0.f, a1 = 0.f, a2 = 0.f;
    int nbo = (t >> 3) + 1;
    #pragma unroll 1
    for (int b = 0; b < nbo; b++) {
        int k0 = b << 3;
        float4 kxA = *(const float4*)&S.K[base + 0][k0];
        float4 kyA = *(const float4*)&S.K[base + 1][k0];
        float4 kzA = *(const float4*)&S.K[base + 2][k0];
        float4 vxA = *(const float4*)&S.V[base + 0][k0];
        float4 vyA = *(const float4*)&S.V[base + 1][k0];
        float4 vzA = *(const float4*)&S.V[base + 2][k0];
        group4(kxA, kyA, kzA, vxA, vyA, vzA, q, t - k0, l, a0, a1, a2);
        if (k0 + 4 <= t) {
            float4 kxB = *(const float4*)&S.K[base + 0][k0 + 4];
            float4 kyB = *(const float4*)&S.K[base + 1][k0 + 4];
            float4 kzB = *(const float4*)&S.K[base + 2][k0 + 4];
            float4 vxB = *(const float4*)&S.V[base + 0][k0 + 4];
            float4 vyB = *(const float4*)&S.V[base + 1][k0 + 4];
            float4 vzB = *(const float4*)&S.V[base + 2][k0 + 4];
            group4(kxB, kyB, kzB, vxB, vyB, vzB, q, t - k0 - 4, l, a0, a1, a2);
        }
    }
    float inv = rcpf(l);
    *(float4*)&S.O[t][qb] = make_float4(a0 * inv, a1 * inv, a2 * inv, 0.f);
}

// Per-position epilogue with LN gains/biases folded into FFN/logit weights.
__device__ __forceinline__ void epilogue_pos(RowShm& R, const float* cw, int t) {
    float4 xa = *(const float4*)&R.X[t][0];
    float2 xb = *(const float2*)&R.X[t][4];
    float4 oa = *(const float4*)&R.O[t][0];
    float4 ob = *(const float4*)&R.O[t][4];
    float o0 = oa.x, o1 = oa.y, o2 = oa.z, o3 = ob.x, o4 = ob.y, o5 = ob.z;
    float xv[6] = { xa.x, xa.y, xa.z, xa.w, xb.x, xb.y };
    float y[6];
    #pragma unroll
    for (int j = 0; j < 6; j++)
        y[j] = xv[j] + o0 * cw[j] + o1 * cw[6 + j] + o2 * cw[12 + j]
             + o3 * cw[18 + j] + o4 * cw[24 + j] + o5 * cw[30 + j];

    float mu = (y[0] + y[1] + y[2] + y[3] + y[4] + y[5]) * (1.f / 6.f);
    float var = 0.f;
    #pragma unroll
    for (int j = 0; j < 6; j++) { float d = y[j] - mu; var += d * d; }
    float rs = rsqrtf(var * (1.f / 6.f) + 1e-5f);

    float dot0 = 0.f, dot1 = 0.f;
    #pragma unroll
    for (int j = 0; j < 6; j++) { dot0 += y[j] * cw[36 + 2 * j]; dot1 += y[j] * cw[37 + 2 * j]; }
    float f0 = rs * (dot0 - mu * cw[48]) + cw[50];
    float f1 = rs * (dot1 - mu * cw[49]) + cw[51];
    float g0 = 0.5f * f0 * (1.f + erff(f0 * 0.70710678118654752f));
    float g1 = 0.5f * f1 * (1.f + erff(f1 * 0.70710678118654752f));
    float z[6];
    #pragma unroll
    for (int j = 0; j < 6; j++) z[j] = y[j] + g0 * cw[52 + j] + g1 * cw[58 + j] + cw[64 + j];

    float mu2 = (z[0] + z[1] + z[2] + z[3] + z[4] + z[5]) * (1.f / 6.f);
    float var2 = 0.f;
    #pragma unroll
    for (int j = 0; j < 6; j++) { float d = z[j] - mu2; var2 += d * d; }
    float rs2 = rsqrtf(var2 * (1.f / 6.f) + 1e-5f);

    float* Lp = (float*)&R.K[0][0];
    #pragma unroll
    for (int n = 0; n < 14; n++) {
        const float* Wn = &cw[70 + n * 6];
        float d = z[0] * Wn[0] + z[1] * Wn[1] + z[2] * Wn[2]
                + z[3] * Wn[3] + z[4] * Wn[4] + z[5] * Wn[5];
        Lp[t * 14 + n] = rs2 * (d - mu2 * cw[154 + n]) + cw[168 + n];
    }
}

__global__ void __launch_bounds__(256, 3)
fwd_kernel(const int* __restrict__ idx, float* __restrict__ out, int nrows)
{
    __shared__ RowShm shm[RPB];
    __shared__ float cw[182];

    int tid = threadIdx.x;
    if (tid < 182) cw[tid] = g_packed[tid];

    int w = tid >> 5, lane = tid & 31;
    int r = w >> 1;            // local row 0..3
    int sub = w & 1;           // head / gather-half
    int row = blockIdx.x * RPB + r;
    bool rowActive = row < nrows;
    RowShm& S = shm[r];

    // ---- phase 2: two warps gather one row (17 positions each) ----
    if (rowActive) {
        // zero pad columns 34..39: warp sub=0 does K, sub=1 does V
        for (int i = lane; i < 36; i += 32) {
            int j = i / 6, tt = 34 + i % 6;
            if (sub == 0) S.K[j][tt] = 0.f; else S.V[j][tt] = 0.f;
        }
        if (lane < 17) {
            int t = sub * 17 + lane;
            int c = idx[(size_t)row * 34 + t];
            const float4* Tp = (const float4*)&g_TAB[(t * 14 + c) * 24];
            float4 v0 = Tp[0], v1 = Tp[1], v2 = Tp[2], v3 = Tp[3], v4 = Tp[4], v5 = Tp[5];
            *(float4*)&S.Q[t][0] = make_float4(v0.x, v0.y, v0.z, 0.f);
            *(float4*)&S.Q[t][4] = make_float4(v0.w, v1.x, v1.y, 0.f);
            S.K[0][t] = v1.z; S.K[1][t] = v1.w; S.K[2][t] = v2.x;
            S.K[3][t] = v2.y; S.K[4][t] = v2.z; S.K[5][t] = v2.w;
            S.V[0][t] = v3.x; S.V[1][t] = v3.y; S.V[2][t] = v3.z;
            S.V[3][t] = v3.w; S.V[4][t] = v4.x; S.V[5][t] = v4.y;
            *(float4*)&S.X[t][0] = make_float4(v4.z, v4.w, v5.x, v5.y);
            *(float2*)&S.X[t][4] = make_float2(v5.z, v5.w);
        }
    }
    __syncthreads();

    // ---- phase 3: warp = (row, head); lane i -> query t=i+2; lane 0 adds t=0,1 ----
    if (rowActive) {
        int h = sub, base = 3 * h, qb = 4 * h;
        attn_one(S, h, lane + 2);
        if (lane == 0) {
            // t = 0: softmax over 1 key -> O = V[:,0]
            *(float4*)&S.O[0][qb] = make_float4(S.V[base + 0][0], S.V[base + 1][0], S.V[base + 2][0], 0.f);
            // t = 1: 2-key softmax
            float4 q = *(const float4*)&S.Q[1][qb];
            float s0 = q.x * S.K[base + 0][0] + q.y * S.K[base + 1][0] + q.z * S.K[base + 2][0];
            float s1 = q.x * S.K[base + 0][1] + q.y * S.K[base + 1][1] + q.z * S.K[base + 2][1];
            float p0 = ex2f(s0), p1 = ex2f(s1);
            float inv = rcpf(p0 + p1);
            *(float4*)&S.O[1][qb] = make_float4(
                (p0 * S.V[base + 0][0] + p1 * S.V[base + 0][1]) * inv,
                (p0 * S.V[base + 1][0] + p1 * S.V[base + 1][1]) * inv,
                (p0 * S.V[base + 2][0] + p1 * S.V[base + 2][1]) * inv, 0.f);
        }
    }
    __syncthreads();

    int blockRows = nrows - blockIdx.x * RPB;
    if (blockRows > RPB) blockRows = RPB;

    // ---- phase 4: block-wide epilogue, 1 task per thread (4*34 = 136 <= 256) ----
    if (tid < blockRows * 34) {
        int rr = tid / 34, t = tid - rr * 34;
        epilogue_pos(shm[rr], cw, t);
    }
    __syncthreads();

    // ---- phase 5: coalesced float4 store (119 float4 per row) ----
    float4* outv = (float4*)out;
    size_t outBase = (size_t)blockIdx.x * RPB * 119;
    int total4 = blockRows * 119;
    for (int i = tid; i < total4; i += 256) {
        int rr = i / 119, q = i - rr * 119;
        outv[outBase + (size_t)rr * 119 + q] = ((const float4*)&shm[rr].K[0][0])[q];
    }
}

// ---------------- launch ----------------

extern "C" void kernel_launch(void* const* d_in, const int* in_sizes, int n_in,
                              void* d_out, int out_size)
{
    const int* idx         = (const int*)d_in[0];
    const float* tok_emb   = (const float*)d_in[1];
    const float* pos_params= (const float*)d_in[2];
    const float* z10_enc   = (const float*)d_in[3];
    const float* special   = (const float*)d_in[4];
    const float* wq        = (const float*)d_in[5];
    const float* wk        = (const float*)d_in[6];
    const float* wv        = (const float*)d_in[7];
    const float* wo        = (const float*)d_in[8];
    const float* ln1_g     = (const float*)d_in[9];
    const float* ln1_b     = (const float*)d_in[10];
    const float* ln2_g     = (const float*)d_in[11];
    const float* ln2_b     = (const float*)d_in[12];
    const float* lnf_g     = (const float*)d_in[13];
    const float* lnf_b     = (const float*)d_in[14];
    const float* ffn_w1    = (const float*)d_in[15];
    const float* ffn_b1    = (const float*)d_in[16];
    const float* ffn_w2    = (const float*)d_in[17];
    const float* ffn_b2    = (const float*)d_in[18];
    const float* head_w    = (const float*)d_in[19];

    int nrows = in_sizes[0] / 34;

    setup_kernel<<<1, 512>>>(tok_emb, pos_params, z10_enc, special,
                             wq, wk, wv, ln1_g, ln1_b,
                             wo, ln2_g, ln2_b, lnf_g, lnf_b,
                             ffn_w1, ffn_b1, ffn_w2, ffn_b2, head_w);

    int grid = (nrows + RPB - 1) / RPB;
    fwd_kernel<<<grid, 256>>>(idx, (float*)d_out, nrows);
}

// round 8
// speedup vs baseline: 1.6373x; 1.0054x over previous
#include <cuda_runtime.h>
#include <math.h>

#define RPB 4   // rows per block (2 warps per row: one per head)

// ---------------- precomputed tables ----------------
// Interleaved per (t,c): [0:6)=Q (pre-scaled by log2(e)/sqrt(3)), [6:12)=K, [12:18)=V, [18:24)=X
__device__ __align__(16) float g_TAB[34 * 14 * 24];
// Packed, 16B-aligned epilogue constants (200 floats = 50 float4):
//  [0:48)    wo padded: row i (o-index) = 8 floats, [i*8+j] = wo[i][j], j<6
//  [48:60)   fw1 folded w/ ln2_g, interleaved [j][m]: [48 + 2j + m]
//  [60:64)   (cs1_0, cs1_1, b1c_0, b1c_1)
//  [64:80)   fw2 padded: row m = 8 floats
//  [80:88)   fb2 padded to 8
//  [88:200)  14 logit blocks of 8: (lnf_g[j]*W[n][j] j=0..5, csf[n], bf[n])
__device__ __align__(16) float g_packed[200];

__device__ __forceinline__ int flatmap(int p) {
    if (p < 10) return p;
    if (p == 10) return 11;
    if (p < 21) return p - 11;
    if (p == 21) return 12;
    if (p < 33) { int z = p - 22; return z < 10 ? z : 10; }
    return 13;
}

__global__ void setup_kernel(const float* __restrict__ tok_emb, const float* __restrict__ pos_params,
                             const float* __restrict__ z10, const float* __restrict__ spec,
                             const float* __restrict__ wq, const float* __restrict__ wk,
                             const float* __restrict__ wv,
                             const float* __restrict__ ln1_g, const float* __restrict__ ln1_b,
                             const float* __restrict__ wo, const float* __restrict__ ln2_g,
                             const float* __restrict__ ln2_b,
                             const float* __restrict__ lnf_g, const float* __restrict__ lnf_b,
                             const float* __restrict__ fw1, const float* __restrict__ fb1,
                             const float* __restrict__ fw2, const float* __restrict__ fb2,
                             const float* __restrict__ head_w)
{
    int tid = threadIdx.x;

    if (tid < 200) {
        float v = 0.f;
        if (tid < 48) {                                   // wo padded rows
            int i = tid >> 3, j = tid & 7;
            v = (j < 6) ? wo[i * 6 + j] : 0.f;
        } else if (tid < 60) {                            // folded fw1, interleaved [j][m]
            int u = tid - 48; int j = u >> 1, m = u & 1;
            v = ln2_g[j] * fw1[j * 2 + m];
        } else if (tid < 62) {                            // column sums of folded fw1
            int m = tid - 60; float s = 0.f;
            for (int j = 0; j < 6; j++) s += ln2_g[j] * fw1[j * 2 + m];
            v = s;
        } else if (tid < 64) {                            // bias via ln2_b
            int m = tid - 62; float s = fb1[m];
            for (int j = 0; j < 6; j++) s += ln2_b[j] * fw1[j * 2 + m];
            v = s;
        } else if (tid < 80) {                            // fw2 padded rows
            int u = tid - 64; int m = u >> 3, j = u & 7;
            v = (j < 6) ? fw2[m * 6 + j] : 0.f;
        } else if (tid < 88) {                            // fb2 padded
            int j = tid - 80;
            v = (j < 6) ? fb2[j] : 0.f;
        } else {                                          // logit blocks of 8
            int u = tid - 88; int n = u >> 3, j = u & 7;
            if (j < 6) {
                float W = head_w[j * 3 + 0] * tok_emb[n * 3 + 0]
                        + head_w[j * 3 + 1] * tok_emb[n * 3 + 1]
                        + head_w[j * 3 + 2] * tok_emb[n * 3 + 2];
                v = lnf_g[j] * W;
            } else {
                const float* gb = (j == 6) ? lnf_g : lnf_b;
                float s = 0.f;
                for (int jj = 0; jj < 6; jj++) {
                    float W = head_w[jj * 3 + 0] * tok_emb[n * 3 + 0]
                            + head_w[jj * 3 + 1] * tok_emb[n * 3 + 1]
                            + head_w[jj * 3 + 2] * tok_emb[n * 3 + 2];
                    s += gb[jj] * W;
                }
                v = s;
            }
        }
        g_packed[tid] = v;
    }

    for (int i = tid; i < 34 * 14; i += blockDim.x) {
        int t = i / 14, c = i % 14;
        int f = flatmap(t);
        float p0, p1, p2;
        if (f < 10) {
            float amp = pos_params[0], ph = pos_params[1], sl = pos_params[2], of = pos_params[3];
            float ang = 0.62831853071795864f * (float)f + ph;
            p0 = amp * cosf(ang);
            p1 = amp * sinf(ang);
            p2 = sl * (float)f + of;
        } else if (f == 10) {
            p0 = z10[0]; p1 = z10[1]; p2 = z10[2];
        } else {
            int s = f - 11;
            p0 = spec[s * 3 + 0]; p1 = spec[s * 3 + 1]; p2 = spec[s * 3 + 2];
        }
        float x[6] = { tok_emb[c * 3 + 0], tok_emb[c * 3 + 1], tok_emb[c * 3 + 2], p0, p1, p2 };
        float mu = 0.f;
        #pragma unroll
        for (int j = 0; j < 6; j++) mu += x[j];
        mu *= (1.f / 6.f);
        float var = 0.f;
        #pragma unroll
        for (int j = 0; j < 6; j++) { float d = x[j] - mu; var += d * d; }
        var *= (1.f / 6.f);
        float rs = rsqrtf(var + 1e-5f);
        float h[6];
        #pragma unroll
        for (int j = 0; j < 6; j++) h[j] = (x[j] - mu) * rs * ln1_g[j] + ln1_b[j];

        const float QS = 1.4426950408889634f / 1.7320508075688772f;  // log2(e)/sqrt(3)
        float* T = &g_TAB[i * 24];
        #pragma unroll
        for (int j = 0; j < 6; j++) {
            float q  = h[3] * wq[j] + h[4] * wq[6 + j] + h[5] * wq[12 + j];
            float k  = h[3] * wk[j] + h[4] * wk[6 + j] + h[5] * wk[12 + j];
            float vv = h[0] * wv[j] + h[1] * wv[6 + j] + h[2] * wv[12 + j];
            T[j]      = q * QS;
            T[6 + j]  = k;
            T[12 + j] = vv;
            T[18 + j] = x[j];
        }
    }
}

// ---------------- main kernel ----------------

struct __align__(16) RowShm {
    float K[6][40];   // SoA keys, stride 40; cols 34..39 zeroed
    float V[6][40];   // SoA values
    float Q[34][8];   // [t][4h+0..2] = q for head h (16B aligned per head)
    float X[34][8];   // [t][0..5]
    float O[34][8];   // [t][4h+0..2] = attention out head h
    // K+V region (480 floats) reused as the 476-float logits buffer in the epilogue
};

__device__ __forceinline__ float ex2f(float x) {
    float y;
    asm("ex2.approx.ftz.f32 %0, %1;" : "=f"(y) : "f"(x));
    return y;
}
__device__ __forceinline__ float rcpf(float x) {
    float y;
    asm("rcp.approx.ftz.f32 %0, %1;" : "=f"(y) : "f"(x));
    return y;
}

// One 4-key score/accumulate group. rem = t - k0 (>= 0 when called).
__device__ __forceinline__ void group4(
    const float4& kx, const float4& ky, const float4& kz,
    const float4& vx, const float4& vy, const float4& vz,
    const float4& q, int rem,
    float& l, float& a0, float& a1, float& a2)
{
    float p0 = ex2f(q.x * kx.x + q.y * ky.x + q.z * kz.x);
    float p1 = ex2f(q.x * kx.y + q.y * ky.y + q.z * kz.y);
    float p2 = ex2f(q.x * kx.z + q.y * ky.z + q.z * kz.z);
    float p3 = ex2f(q.x * kx.w + q.y * ky.w + q.z * kz.w);
    if (rem < 1) p1 = 0.f;
    if (rem < 2) p2 = 0.f;
    if (rem < 3) p3 = 0.f;
    l  += (p0 + p1) + (p2 + p3);
    a0 += (p0 * vx.x + p1 * vx.y) + (p2 * vx.z + p3 * vx.w);
    a1 += (p0 * vy.x + p1 * vy.y) + (p2 * vy.z + p3 * vy.w);
    a2 += (p0 * vz.x + p1 * vz.y) + (p2 * vz.z + p3 * vz.w);
}

// Single causal-attention task for query t, head h; 8 keys per iteration.
__device__ __forceinline__ void attn_one(RowShm& S, int h, int t) {
    int base = 3 * h, qb = 4 * h;
    float4 q = *(const float4*)&S.Q[t][qb];
    float l = 0.f, a0 = 0.f, a1 = 0.f, a2 = 0.f;
    int nbo = (t >> 3) + 1;
    #pragma unroll 1
    for (int b = 0; b < nbo; b++) {
        int k0 = b << 3;
        float4 kxA = *(const float4*)&S.K[base + 0][k0];
        float4 kyA = *(const float4*)&S.K[base + 1][k0];
        float4 kzA = *(const float4*)&S.K[base + 2][k0];
        float4 vxA = *(const float4*)&S.V[base + 0][k0];
        float4 vyA = *(const float4*)&S.V[base + 1][k0];
        float4 vzA = *(const float4*)&S.V[base + 2][k0];
        group4(kxA, kyA, kzA, vxA, vyA, vzA, q, t - k0, l, a0, a1, a2);
        if (k0 + 4 <= t) {
            float4 kxB = *(const float4*)&S.K[base + 0][k0 + 4];
            float4 kyB = *(const float4*)&S.K[base + 1][k0 + 4];
            float4 kzB = *(const float4*)&S.K[base + 2][k0 + 4];
            float4 vxB = *(const float4*)&S.V[base + 0][k0 + 4];
            float4 vyB = *(const float4*)&S.V[base + 1][k0 + 4];
            float4 vzB = *(const float4*)&S.V[base + 2][k0 + 4];
            group4(kxB, kyB, kzB, vxB, vyB, vzB, q, t - k0 - 4, l, a0, a1, a2);
        }
    }
    float inv = rcpf(l);
    *(float4*)&S.O[t][qb] = make_float4(a0 * inv, a1 * inv, a2 * inv, 0.f);
}

// Per-position epilogue; all constants read via float4 (broadcast LDS.128).
__device__ __forceinline__ void epilogue_pos(RowShm& R, const float* cw, int t) {
    const float4* c4 = (const float4*)cw;
    float4 xa = *(const float4*)&R.X[t][0];
    float2 xb = *(const float2*)&R.X[t][4];
    float4 oa = *(const float4*)&R.O[t][0];
    float4 ob = *(const float4*)&R.O[t][4];
    float o[6] = { oa.x, oa.y, oa.z, ob.x, ob.y, ob.z };

    // y = X + o @ wo   (wo rows padded to 8 floats -> 2 float4 per row)
    float y0 = xa.x, y1 = xa.y, y2 = xa.z, y3 = xa.w, y4 = xb.x, y5 = xb.y;
    #pragma unroll
    for (int i = 0; i < 6; i++) {
        float4 lo = c4[2 * i], hi = c4[2 * i + 1];
        y0 += o[i] * lo.x; y1 += o[i] * lo.y; y2 += o[i] * lo.z; y3 += o[i] * lo.w;
        y4 += o[i] * hi.x; y5 += o[i] * hi.y;
    }

    // LN2 stats (gain/bias folded into FFN weights)
    float mu = (y0 + y1 + y2 + y3 + y4 + y5) * (1.f / 6.f);
    float var = (y0 - mu) * (y0 - mu) + (y1 - mu) * (y1 - mu) + (y2 - mu) * (y2 - mu)
              + (y3 - mu) * (y3 - mu) + (y4 - mu) * (y4 - mu) + (y5 - mu) * (y5 - mu);
    float rs = rsqrtf(var * (1.f / 6.f) + 1e-5f);

    float4 fa = c4[12], fb = c4[13], fc = c4[14];   // folded fw1, interleaved [j][m]
    float dot0 = y0 * fa.x + y1 * fa.z + y2 * fb.x + y3 * fb.z + y4 * fc.x + y5 * fc.z;
    float dot1 = y0 * fa.y + y1 * fa.w + y2 * fb.y + y3 * fb.w + y4 * fc.y + y5 * fc.w;
    float4 cb = c4[15];                              // (cs0, cs1, b0, b1)
    float f0 = rs * (dot0 - mu * cb.x) + cb.z;
    float f1 = rs * (dot1 - mu * cb.y) + cb.w;
    float g0 = 0.5f * f0 * (1.f + erff(f0 * 0.70710678118654752f));
    float g1 = 0.5f * f1 * (1.f + erff(f1 * 0.70710678118654752f));

    float4 r0lo = c4[16], r0hi = c4[17], r1lo = c4[18], r1hi = c4[19];
    float4 b2lo = c4[20], b2hi = c4[21];
    float z0 = y0 + g0 * r0lo.x + g1 * r1lo.x + b2lo.x;
    float z1 = y1 + g0 * r0lo.y + g1 * r1lo.y + b2lo.y;
    float z2 = y2 + g0 * r0lo.z + g1 * r1lo.z + b2lo.z;
    float z3 = y3 + g0 * r0lo.w + g1 * r1lo.w + b2lo.w;
    float z4 = y4 + g0 * r0hi.x + g1 * r1hi.x + b2hi.x;
    float z5 = y5 + g0 * r0hi.y + g1 * r1hi.y + b2hi.y;

    // LNf stats (gain/bias folded into logit weights)
    float mu2 = (z0 + z1 + z2 + z3 + z4 + z5) * (1.f / 6.f);
    float var2 = (z0 - mu2) * (z0 - mu2) + (z1 - mu2) * (z1 - mu2) + (z2 - mu2) * (z2 - mu2)
               + (z3 - mu2) * (z3 - mu2) + (z4 - mu2) * (z4 - mu2) + (z5 - mu2) * (z5 - mu2);
    float rs2 = rsqrtf(var2 * (1.f / 6.f) + 1e-5f);

    float* Lp = (float*)&R.K[0][0];
    #pragma unroll
    for (int n = 0; n < 14; n++) {
        float4 w0 = c4[22 + 2 * n], w1 = c4[23 + 2 * n];  // (W0..3), (W4,W5,csf,bf)
        float d = z0 * w0.x + z1 * w0.y + z2 * w0.z + z3 * w0.w + z4 * w1.x + z5 * w1.y;
        Lp[t * 14 + n] = rs2 * (d - mu2 * w1.z) + w1.w;
    }
}

__global__ void __launch_bounds__(256, 3)
fwd_kernel(const int* __restrict__ idx, float* __restrict__ out, int nrows)
{
    __shared__ RowShm shm[RPB];
    __shared__ __align__(16) float cw[200];

    int tid = threadIdx.x;
    if (tid < 200) cw[tid] = g_packed[tid];

    int w = tid >> 5, lane = tid & 31;
    int r = w >> 1;            // local row 0..3
    int sub = w & 1;           // head / gather-half
    int row = blockIdx.x * RPB + r;
    bool rowActive = row < nrows;
    RowShm& S = shm[r];

    // ---- phase 2: two warps gather one row (17 positions each) ----
    if (rowActive) {
        for (int i = lane; i < 36; i += 32) {   // zero pad cols: sub0 -> K, sub1 -> V
            int j = i / 6, tt = 34 + i % 6;
            if (sub == 0) S.K[j][tt] = 0.f; else S.V[j][tt] = 0.f;
        }
        if (lane < 17) {
            int t = sub * 17 + lane;
            int c = idx[(size_t)row * 34 + t];
            const float4* Tp = (const float4*)&g_TAB[(t * 14 + c) * 24];
            float4 v0 = Tp[0], v1 = Tp[1], v2 = Tp[2], v3 = Tp[3], v4 = Tp[4], v5 = Tp[5];
            *(float4*)&S.Q[t][0] = make_float4(v0.x, v0.y, v0.z, 0.f);
            *(float4*)&S.Q[t][4] = make_float4(v0.w, v1.x, v1.y, 0.f);
            S.K[0][t] = v1.z; S.K[1][t] = v1.w; S.K[2][t] = v2.x;
            S.K[3][t] = v2.y; S.K[4][t] = v2.z; S.K[5][t] = v2.w;
            S.V[0][t] = v3.x; S.V[1][t] = v3.y; S.V[2][t] = v3.z;
            S.V[3][t] = v3.w; S.V[4][t] = v4.x; S.V[5][t] = v4.y;
            *(float4*)&S.X[t][0] = make_float4(v4.z, v4.w, v5.x, v5.y);
            *(float2*)&S.X[t][4] = make_float2(v5.z, v5.w);
        }
    }
    __syncthreads();

    // ---- phase 3: warp = (row, head); lane i -> query t=i+2; lane 0 adds t=0,1 ----
    if (rowActive) {
        int h = sub, base = 3 * h, qb = 4 * h;
        attn_one(S, h, lane + 2);
        if (lane == 0) {
            *(float4*)&S.O[0][qb] = make_float4(S.V[base + 0][0], S.V[base + 1][0], S.V[base + 2][0], 0.f);
            float4 q = *(const float4*)&S.Q[1][qb];
            float s0 = q.x * S.K[base + 0][0] + q.y * S.K[base + 1][0] + q.z * S.K[base + 2][0];
            float s1 = q.x * S.K[base + 0][1] + q.y * S.K[base + 1][1] + q.z * S.K[base + 2][1];
            float p0 = ex2f(s0), p1 = ex2f(s1);
            float inv = rcpf(p0 + p1);
            *(float4*)&S.O[1][qb] = make_float4(
                (p0 * S.V[base + 0][0] + p1 * S.V[base + 0][1]) * inv,
                (p0 * S.V[base + 1][0] + p1 * S.V[base + 1][1]) * inv,
                (p0 * S.V[base + 2][0] + p1 * S.V[base + 2][1]) * inv, 0.f);
        }
    }
    __syncthreads();

    int blockRows = nrows - blockIdx.x * RPB;
    if (blockRows > RPB) blockRows = RPB;

    // ---- phase 4: block-wide epilogue, 1 task per thread (4*34 = 136 <= 256) ----
    if (tid < blockRows * 34) {
        int rr = tid / 34, t = tid - rr * 34;
        epilogue_pos(shm[rr], cw, t);
    }
    __syncthreads();

    // ---- phase 5: coalesced float4 store (119 float4 per row) ----
    float4* outv = (float4*)out;
    size_t outBase = (size_t)blockIdx.x * RPB * 119;
    int total4 = blockRows * 119;
    for (int i = tid; i < total4; i += 256) {
        int rr = i / 119, q = i - rr * 119;
        outv[outBase + (size_t)rr * 119 + q] = ((const float4*)&shm[rr].K[0][0])[q];
    }
}

// ---------------- launch ----------------

extern "C" void kernel_launch(void* const* d_in, const int* in_sizes, int n_in,
                              void* d_out, int out_size)
{
    const int* idx         = (const int*)d_in[0];
    const float* tok_emb   = (const float*)d_in[1];
    const float* pos_params= (const float*)d_in[2];
    const float* z10_enc   = (const float*)d_in[3];
    const float* special   = (const float*)d_in[4];
    const float* wq        = (const float*)d_in[5];
    const float* wk        = (const float*)d_in[6];
    const float* wv        = (const float*)d_in[7];
    const float* wo        = (const float*)d_in[8];
    const float* ln1_g     = (const float*)d_in[9];
    const float* ln1_b     = (const float*)d_in[10];
    const float* ln2_g     = (const float*)d_in[11];
    const float* ln2_b     = (const float*)d_in[12];
    const float* lnf_g     = (const float*)d_in[13];
    const float* lnf_b     = (const float*)d_in[14];
    const float* ffn_w1    = (const float*)d_in[15];
    const float* ffn_b1    = (const float*)d_in[16];
    const float* ffn_w2    = (const float*)d_in[17];
    const float* ffn_b2    = (const float*)d_in[18];
    const float* head_w    = (const float*)d_in[19];

    int nrows = in_sizes[0] / 34;

    setup_kernel<<<1, 512>>>(tok_emb, pos_params, z10_enc, special,
                             wq, wk, wv, ln1_g, ln1_b,
                             wo, ln2_g, ln2_b, lnf_g, lnf_b,
                             ffn_w1, ffn_b1, ffn_w2, ffn_b2, head_w);

    int grid = (nrows + RPB - 1) / RPB;
    fwd_kernel<<<grid, 256>>>(idx, (float*)d_out, nrows);
}

// round 9
// speedup vs baseline: 1.6391x; 1.0011x over previous
#include <cuda_runtime.h>
#include <math.h>

#define RPB 4   // rows per block (2 warps per row: one per head)

// ---------------- precomputed tables ----------------
// Interleaved per (t,c): [0:6)=Q (pre-scaled by log2(e)/sqrt(3)), [6:12)=K, [12:18)=V, [18:24)=X
__device__ __align__(16) float g_TAB[34 * 14 * 24];
// Packed, 16B-aligned epilogue constants (200 floats = 50 float4):
//  [0:48)    wo padded: row i (o-index) = 8 floats
//  [48:60)   fw1 folded w/ ln2_g, interleaved [j][m]
//  [60:64)   (cs1_0, cs1_1, b1c_0, b1c_1)
//  [64:80)   fw2 padded rows
//  [80:88)   fb2 padded
//  [88:200)  14 logit blocks of 8: (lnf_g[j]*W[n][j] j=0..5, csf[n], bf[n])
__device__ __align__(16) float g_packed[200];

__device__ __forceinline__ int flatmap(int p) {
    if (p < 10) return p;
    if (p == 10) return 11;
    if (p < 21) return p - 11;
    if (p == 21) return 12;
    if (p < 33) { int z = p - 22; return z < 10 ? z : 10; }
    return 13;
}

__global__ void setup_kernel(const float* __restrict__ tok_emb, const float* __restrict__ pos_params,
                             const float* __restrict__ z10, const float* __restrict__ spec,
                             const float* __restrict__ wq, const float* __restrict__ wk,
                             const float* __restrict__ wv,
                             const float* __restrict__ ln1_g, const float* __restrict__ ln1_b,
                             const float* __restrict__ wo, const float* __restrict__ ln2_g,
                             const float* __restrict__ ln2_b,
                             const float* __restrict__ lnf_g, const float* __restrict__ lnf_b,
                             const float* __restrict__ fw1, const float* __restrict__ fb1,
                             const float* __restrict__ fw2, const float* __restrict__ fb2,
                             const float* __restrict__ head_w)
{
    int tid = threadIdx.x;

    if (tid < 200) {
        float v = 0.f;
        if (tid < 48) {
            int i = tid >> 3, j = tid & 7;
            v = (j < 6) ? wo[i * 6 + j] : 0.f;
        } else if (tid < 60) {
            int u = tid - 48; int j = u >> 1, m = u & 1;
            v = ln2_g[j] * fw1[j * 2 + m];
        } else if (tid < 62) {
            int m = tid - 60; float s = 0.f;
            for (int j = 0; j < 6; j++) s += ln2_g[j] * fw1[j * 2 + m];
            v = s;
        } else if (tid < 64) {
            int m = tid - 62; float s = fb1[m];
            for (int j = 0; j < 6; j++) s += ln2_b[j] * fw1[j * 2 + m];
            v = s;
        } else if (tid < 80) {
            int u = tid - 64; int m = u >> 3, j = u & 7;
            v = (j < 6) ? fw2[m * 6 + j] : 0.f;
        } else if (tid < 88) {
            int j = tid - 80;
            v = (j < 6) ? fb2[j] : 0.f;
        } else {
            int u = tid - 88; int n = u >> 3, j = u & 7;
            if (j < 6) {
                float W = head_w[j * 3 + 0] * tok_emb[n * 3 + 0]
                        + head_w[j * 3 + 1] * tok_emb[n * 3 + 1]
                        + head_w[j * 3 + 2] * tok_emb[n * 3 + 2];
                v = lnf_g[j] * W;
            } else {
                const float* gb = (j == 6) ? lnf_g : lnf_b;
                float s = 0.f;
                for (int jj = 0; jj < 6; jj++) {
                    float W = head_w[jj * 3 + 0] * tok_emb[n * 3 + 0]
                            + head_w[jj * 3 + 1] * tok_emb[n * 3 + 1]
                            + head_w[jj * 3 + 2] * tok_emb[n * 3 + 2];
                    s += gb[jj] * W;
                }
                v = s;
            }
        }
        g_packed[tid] = v;
    }

    for (int i = tid; i < 34 * 14; i += blockDim.x) {
        int t = i / 14, c = i % 14;
        int f = flatmap(t);
        float p0, p1, p2;
        if (f < 10) {
            float amp = pos_params[0], ph = pos_params[1], sl = pos_params[2], of = pos_params[3];
            float ang = 0.62831853071795864f * (float)f + ph;
            p0 = amp * cosf(ang);
            p1 = amp * sinf(ang);
            p2 = sl * (float)f + of;
        } else if (f == 10) {
            p0 = z10[0]; p1 = z10[1]; p2 = z10[2];
        } else {
            int s = f - 11;
            p0 = spec[s * 3 + 0]; p1 = spec[s * 3 + 1]; p2 = spec[s * 3 + 2];
        }
        float x[6] = { tok_emb[c * 3 + 0], tok_emb[c * 3 + 1], tok_emb[c * 3 + 2], p0, p1, p2 };
        float mu = 0.f;
        #pragma unroll
        for (int j = 0; j < 6; j++) mu += x[j];
        mu *= (1.f / 6.f);
        float var = 0.f;
        #pragma unroll
        for (int j = 0; j < 6; j++) { float d = x[j] - mu; var += d * d; }
        var *= (1.f / 6.f);
        float rs = rsqrtf(var + 1e-5f);
        float h[6];
        #pragma unroll
        for (int j = 0; j < 6; j++) h[j] = (x[j] - mu) * rs * ln1_g[j] + ln1_b[j];

        const float QS = 1.4426950408889634f / 1.7320508075688772f;  // log2(e)/sqrt(3)
        float* T = &g_TAB[i * 24];
        #pragma unroll
        for (int j = 0; j < 6; j++) {
            float q  = h[3] * wq[j] + h[4] * wq[6 + j] + h[5] * wq[12 + j];
            float k  = h[3] * wk[j] + h[4] * wk[6 + j] + h[5] * wk[12 + j];
            float vv = h[0] * wv[j] + h[1] * wv[6 + j] + h[2] * wv[12 + j];
            T[j]      = q * QS;
            T[6 + j]  = k;
            T[12 + j] = vv;
            T[18 + j] = x[j];
        }
    }
}

// ---------------- main kernel ----------------

struct __align__(16) RowShm {
    float K[6][40];   // SoA keys, stride 40; cols 34..39 zeroed
    float V[6][40];   // SoA values
    float Q[34][8];   // [t][4h+0..2] = q for head h
    float X[34][8];   // [t][0..5]
    float O[34][8];   // [t][4h+0..2] = attention out head h
    // K+V region (480 floats) reused as the 476-float logits buffer in the epilogue
};

__device__ __forceinline__ float ex2f(float x) {
    float y;
    asm("ex2.approx.ftz.f32 %0, %1;" : "=f"(y) : "f"(x));
    return y;
}
__device__ __forceinline__ float rcpf(float x) {
    float y;
    asm("rcp.approx.ftz.f32 %0, %1;" : "=f"(y) : "f"(x));
    return y;
}

// One 4-key score/accumulate group. rem = t - k0 (>= 0 when called).
__device__ __forceinline__ void group4(
    const float4& kx, const float4& ky, const float4& kz,
    const float4& vx, const float4& vy, const float4& vz,
    const float4& q, int rem,
    float& l, float& a0, float& a1, float& a2)
{
    float p0 = ex2f(q.x * kx.x + q.y * ky.x + q.z * kz.x);
    float p1 = ex2f(q.x * kx.y + q.y * ky.y + q.z * kz.y);
    float p2 = ex2f(q.x * kx.z + q.y * ky.z + q.z * kz.z);
    float p3 = ex2f(q.x * kx.w + q.y * ky.w + q.z * kz.w);
    if (rem < 1) p1 = 0.f;
    if (rem < 2) p2 = 0.f;
    if (rem < 3) p3 = 0.f;
    l  += (p0 + p1) + (p2 + p3);
    a0 += (p0 * vx.x + p1 * vx.y) + (p2 * vx.z + p3 * vx.w);
    a1 += (p0 * vy.x + p1 * vy.y) + (p2 * vy.z + p3 * vy.w);
    a2 += (p0 * vz.x + p1 * vz.y) + (p2 * vz.z + p3 * vz.w);
}

// Single causal-attention task for query t, head h; 8 keys per iteration.
__device__ __forceinline__ void attn_one(RowShm& S, int h, int t) {
    int base = 3 * h, qb = 4 * h;
    float4 q = *(const float4*)&S.Q[t][qb];
    float l = 0.f, a0 = 0.f, a1 = 0.f, a2 = 0.f;
    int nbo = (t >> 3) + 1;
    #pragma unroll 1
    for (int b = 0; b < nbo; b++) {
        int k0 = b << 3;
        float4 kxA = *(const float4*)&S.K[base + 0][k0];
        float4 kyA = *(const float4*)&S.K[base + 1][k0];
        float4 kzA = *(const float4*)&S.K[base + 2][k0];
        float4 vxA = *(const float4*)&S.V[base + 0][k0];
        float4 vyA = *(const float4*)&S.V[base + 1][k0];
        float4 vzA = *(const float4*)&S.V[base + 2][k0];
        group4(kxA, kyA, kzA, vxA, vyA, vzA, q, t - k0, l, a0, a1, a2);
        if (k0 + 4 <= t) {
            float4 kxB = *(const float4*)&S.K[base + 0][k0 + 4];
            float4 kyB = *(const float4*)&S.K[base + 1][k0 + 4];
            float4 kzB = *(const float4*)&S.K[base + 2][k0 + 4];
            float4 vxB = *(const float4*)&S.V[base + 0][k0 + 4];
            float4 vyB = *(const float4*)&S.V[base + 1][k0 + 4];
            float4 vzB = *(const float4*)&S.V[base + 2][k0 + 4];
            group4(kxB, kyB, kzB, vxB, vyB, vzB, q, t - k0 - 4, l, a0, a1, a2);
        }
    }
    float inv = rcpf(l);
    *(float4*)&S.O[t][qb] = make_float4(a0 * inv, a1 * inv, a2 * inv, 0.f);
}

// Per-position epilogue; constants read via float4, logits stored as float2 pairs.
__device__ __forceinline__ void epilogue_pos(RowShm& R, const float* cw, int t) {
    const float4* c4 = (const float4*)cw;
    float4 xa = *(const float4*)&R.X[t][0];
    float2 xb = *(const float2*)&R.X[t][4];
    float4 oa = *(const float4*)&R.O[t][0];
    float4 ob = *(const float4*)&R.O[t][4];
    float o[6] = { oa.x, oa.y, oa.z, ob.x, ob.y, ob.z };

    float y0 = xa.x, y1 = xa.y, y2 = xa.z, y3 = xa.w, y4 = xb.x, y5 = xb.y;
    #pragma unroll
    for (int i = 0; i < 6; i++) {
        float4 lo = c4[2 * i], hi = c4[2 * i + 1];
        y0 += o[i] * lo.x; y1 += o[i] * lo.y; y2 += o[i] * lo.z; y3 += o[i] * lo.w;
        y4 += o[i] * hi.x; y5 += o[i] * hi.y;
    }

    float mu = (y0 + y1 + y2 + y3 + y4 + y5) * (1.f / 6.f);
    float var = (y0 - mu) * (y0 - mu) + (y1 - mu) * (y1 - mu) + (y2 - mu) * (y2 - mu)
              + (y3 - mu) * (y3 - mu) + (y4 - mu) * (y4 - mu) + (y5 - mu) * (y5 - mu);
    float rs = rsqrtf(var * (1.f / 6.f) + 1e-5f);

    float4 fa = c4[12], fb = c4[13], fc = c4[14];
    float dot0 = y0 * fa.x + y1 * fa.z + y2 * fb.x + y3 * fb.z + y4 * fc.x + y5 * fc.z;
    float dot1 = y0 * fa.y + y1 * fa.w + y2 * fb.y + y3 * fb.w + y4 * fc.y + y5 * fc.w;
    float4 cb = c4[15];
    float f0 = rs * (dot0 - mu * cb.x) + cb.z;
    float f1 = rs * (dot1 - mu * cb.y) + cb.w;
    float g0 = 0.5f * f0 * (1.f + erff(f0 * 0.70710678118654752f));
    float g1 = 0.5f * f1 * (1.f + erff(f1 * 0.70710678118654752f));

    float4 r0lo = c4[16], r0hi = c4[17], r1lo = c4[18], r1hi = c4[19];
    float4 b2lo = c4[20], b2hi = c4[21];
    float z0 = y0 + g0 * r0lo.x + g1 * r1lo.x + b2lo.x;
    float z1 = y1 + g0 * r0lo.y + g1 * r1lo.y + b2lo.y;
    float z2 = y2 + g0 * r0lo.z + g1 * r1lo.z + b2lo.z;
    float z3 = y3 + g0 * r0lo.w + g1 * r1lo.w + b2lo.w;
    float z4 = y4 + g0 * r0hi.x + g1 * r1hi.x + b2hi.x;
    float z5 = y5 + g0 * r0hi.y + g1 * r1hi.y + b2hi.y;

    float mu2 = (z0 + z1 + z2 + z3 + z4 + z5) * (1.f / 6.f);
    float var2 = (z0 - mu2) * (z0 - mu2) + (z1 - mu2) * (z1 - mu2) + (z2 - mu2) * (z2 - mu2)
               + (z3 - mu2) * (z3 - mu2) + (z4 - mu2) * (z4 - mu2) + (z5 - mu2) * (z5 - mu2);
    float rs2 = rsqrtf(var2 * (1.f / 6.f) + 1e-5f);

    // Logits packed 14 per position; 56t bytes is always 8B-aligned -> 7x STS.64
    float2* Lp2 = (float2*)((float*)&R.K[0][0] + t * 14);
    #pragma unroll
    for (int n = 0; n < 14; n += 2) {
        float4 w0 = c4[22 + 2 * n], w1 = c4[23 + 2 * n];
        float4 u0 = c4[24 + 2 * n], u1 = c4[25 + 2 * n];
        float da = z0 * w0.x + z1 * w0.y + z2 * w0.z + z3 * w0.w + z4 * w1.x + z5 * w1.y;
        float db = z0 * u0.x + z1 * u0.y + z2 * u0.z + z3 * u0.w + z4 * u1.x + z5 * u1.y;
        float la = rs2 * (da - mu2 * w1.z) + w1.w;
        float lb = rs2 * (db - mu2 * u1.z) + u1.w;
        Lp2[n >> 1] = make_float2(la, lb);
    }
}

__global__ void __launch_bounds__(256, 4)
fwd_kernel(const int* __restrict__ idx, float* __restrict__ out, int nrows)
{
    __shared__ RowShm shm[RPB];
    __shared__ __align__(16) float cw[200];

    int tid = threadIdx.x;
    if (tid < 200) cw[tid] = g_packed[tid];

    int w = tid >> 5, lane = tid & 31;
    int r = w >> 1;            // local row 0..3
    int sub = w & 1;           // head / gather-half
    int row = blockIdx.x * RPB + r;
    bool rowActive = row < nrows;
    RowShm& S = shm[r];

    // ---- phase 2: two warps gather one row (17 positions each) ----
    if (rowActive) {
        for (int i = lane; i < 36; i += 32) {   // zero pad cols: sub0 -> K, sub1 -> V
            int j = i / 6, tt = 34 + i % 6;
            if (sub == 0) S.K[j][tt] = 0.f; else S.V[j][tt] = 0.f;
        }
        if (lane < 17) {
            int t = sub * 17 + lane;
            int c = idx[(size_t)row * 34 + t];
            const float4* Tp = (const float4*)&g_TAB[(t * 14 + c) * 24];
            float4 v0 = Tp[0], v1 = Tp[1], v2 = Tp[2], v3 = Tp[3], v4 = Tp[4], v5 = Tp[5];
            *(float4*)&S.Q[t][0] = make_float4(v0.x, v0.y, v0.z, 0.f);
            *(float4*)&S.Q[t][4] = make_float4(v0.w, v1.x, v1.y, 0.f);
            S.K[0][t] = v1.z; S.K[1][t] = v1.w; S.K[2][t] = v2.x;
            S.K[3][t] = v2.y; S.K[4][t] = v2.z; S.K[5][t] = v2.w;
            S.V[0][t] = v3.x; S.V[1][t] = v3.y; S.V[2][t] = v3.z;
            S.V[3][t] = v3.w; S.V[4][t] = v4.x; S.V[5][t] = v4.y;
            *(float4*)&S.X[t][0] = make_float4(v4.z, v4.w, v5.x, v5.y);
            *(float2*)&S.X[t][4] = make_float2(v5.z, v5.w);
        }
    }
    __syncthreads();

    // ---- phase 3: warp = (row, head); lane i -> query t=i+2; lane 0 adds t=0,1 ----
    if (rowActive) {
        int h = sub, base = 3 * h, qb = 4 * h;
        attn_one(S, h, lane + 2);
        if (lane == 0) {
            *(float4*)&S.O[0][qb] = make_float4(S.V[base + 0][0], S.V[base + 1][0], S.V[base + 2][0], 0.f);
            float4 q = *(const float4*)&S.Q[1][qb];
            float s0 = q.x * S.K[base + 0][0] + q.y * S.K[base + 1][0] + q.z * S.K[base + 2][0];
            float s1 = q.x * S.K[base + 0][1] + q.y * S.K[base + 1][1] + q.z * S.K[base + 2][1];
            float p0 = ex2f(s0), p1 = ex2f(s1);
            float inv = rcpf(p0 + p1);
            *(float4*)&S.O[1][qb] = make_float4(
                (p0 * S.V[base + 0][0] + p1 * S.V[base + 0][1]) * inv,
                (p0 * S.V[base + 1][0] + p1 * S.V[base + 1][1]) * inv,
                (p0 * S.V[base + 2][0] + p1 * S.V[base + 2][1]) * inv, 0.f);
        }
    }
    __syncthreads();

    int blockRows = nrows - blockIdx.x * RPB;
    if (blockRows > RPB) blockRows = RPB;

    // ---- phase 4: block-wide epilogue, 1 task per thread (4*34 = 136 <= 256) ----
    if (tid < blockRows * 34) {
        int rr = tid / 34, t = tid - rr * 34;
        epilogue_pos(shm[rr], cw, t);
    }
    __syncthreads();

    // ---- phase 5: coalesced float4 store (119 float4 per row) ----
    float4* outv = (float4*)out;
    size_t outBase = (size_t)blockIdx.x * RPB * 119;
    int total4 = blockRows * 119;
    for (int i = tid; i < total4; i += 256) {
        int rr = i / 119, q = i - rr * 119;
        outv[outBase + (size_t)rr * 119 + q] = ((const float4*)&shm[rr].K[0][0])[q];
    }
}

// ---------------- launch ----------------

extern "C" void kernel_launch(void* const* d_in, const int* in_sizes, int n_in,
                              void* d_out, int out_size)
{
    const int* idx         = (const int*)d_in[0];
    const float* tok_emb   = (const float*)d_in[1];
    const float* pos_params= (const float*)d_in[2];
    const float* z10_enc   = (const float*)d_in[3];
    const float* special   = (const float*)d_in[4];
    const float* wq        = (const float*)d_in[5];
    const float* wk        = (const float*)d_in[6];
    const float* wv        = (const float*)d_in[7];
    const float* wo        = (const float*)d_in[8];
    const float* ln1_g     = (const float*)d_in[9];
    const float* ln1_b     = (const float*)d_in[10];
    const float* ln2_g     = (const float*)d_in[11];
    const float* ln2_b     = (const float*)d_in[12];
    const float* lnf_g     = (const float*)d_in[13];
    const float* lnf_b     = (const float*)d_in[14];
    const float* ffn_w1    = (const float*)d_in[15];
    const float* ffn_b1    = (const float*)d_in[16];
    const float* ffn_w2    = (const float*)d_in[17];
    const float* ffn_b2    = (const float*)d_in[18];
    const float* head_w    = (const float*)d_in[19];

    int nrows = in_sizes[0] / 34;

    setup_kernel<<<1, 512>>>(tok_emb, pos_params, z10_enc, special,
                             wq, wk, wv, ln1_g, ln1_b,
                             wo, ln2_g, ln2_b, lnf_g, lnf_b,
                             ffn_w1, ffn_b1, ffn_w2, ffn_b2, head_w);

    int grid = (nrows + RPB - 1) / RPB;
    fwd_kernel<<<grid, 256>>>(idx, (float*)d_out, nrows);
}